// round 3
// baseline (speedup 1.0000x reference)
#include <cuda_runtime.h>
#include <cuda_bf16.h>

#define MAXN 50000
#define MAXE 600000
#define L 128
#define INF 7

typedef unsigned long long ull;

// ---------------- device scratch (no allocations allowed) ----------------
__device__ float g_h[MAXN * L];
__device__ float g_t0[MAXN * L];
__device__ float g_t1[MAXN * L];
__device__ float g_inv_s[MAXN];
__device__ float g_inv_r[MAXN];
__device__ int   g_deg_s[MAXN];
__device__ int   g_deg_r[MAXN];
__device__ int   g_row[MAXN];
__device__ int   g_fill[MAXN];
__device__ int   g_csr_sender[MAXE];
__device__ int   g_total;

// ---------------- f32x2 helpers ----------------
__device__ __forceinline__ ull pk2(float lo, float hi) {
    ull r; asm("mov.b64 %0, {%1,%2};" : "=l"(r) : "f"(lo), "f"(hi)); return r;
}
__device__ __forceinline__ ull ffma2(ull a, ull b, ull c) {
    ull d; asm("fma.rn.f32x2 %0, %1, %2, %3;" : "=l"(d) : "l"(a), "l"(b), "l"(c)); return d;
}
__device__ __forceinline__ float2 upk2(ull v) {
    float lo, hi; asm("mov.b64 {%0,%1}, %2;" : "=f"(lo), "=f"(hi) : "l"(v));
    return make_float2(lo, hi);
}

// ---------------- setup kernels ----------------
__global__ void zero_kernel(int n) {
    int i0 = blockIdx.x * blockDim.x + threadIdx.x;
    if (i0 == 0) g_total = 0;
    for (int i = i0; i < n; i += gridDim.x * blockDim.x) {
        g_deg_s[i] = 0; g_deg_r[i] = 0; g_fill[i] = 0;
    }
}

__global__ void degree_kernel(const int* __restrict__ senders,
                              const int* __restrict__ receivers, int e) {
    for (int t = blockIdx.x * blockDim.x + threadIdx.x; t < e; t += gridDim.x * blockDim.x) {
        atomicAdd(&g_deg_s[senders[t]], 1);
        atomicAdd(&g_deg_r[receivers[t]], 1);
    }
}

// inverse sqrt degrees + atomic CSR row allocation (row order is arbitrary;
// only per-node contiguity matters for the gather).
__global__ void inv_row_kernel(int n) {
    for (int i = blockIdx.x * blockDim.x + threadIdx.x; i < n; i += gridDim.x * blockDim.x) {
        int dr = g_deg_r[i];
        g_inv_s[i] = rsqrtf(fmaxf((float)g_deg_s[i], 1.0f));
        g_inv_r[i] = rsqrtf(fmaxf((float)dr, 1.0f));
        g_row[i] = atomicAdd(&g_total, dr);
    }
}

__global__ void fill_kernel(const int* __restrict__ senders,
                            const int* __restrict__ receivers, int e) {
    for (int t = blockIdx.x * blockDim.x + threadIdx.x; t < e; t += gridDim.x * blockDim.x) {
        int r = receivers[t];
        int p = g_row[r] + atomicAdd(&g_fill[r], 1);
        g_csr_sender[p] = senders[t];
    }
}

// ---------------- embed: h = nodes @ W_embed + b ----------------
__global__ void embed_kernel(const float* __restrict__ nodes,
                             const float* __restrict__ We,
                             const float* __restrict__ be, int n) {
    int i = blockIdx.x * 2 + (threadIdx.x >> 7);
    if (i >= n) return;
    int j = threadIdx.x & 127;
    float s = be[j];
    #pragma unroll
    for (int k = 0; k < INF; k++) s = fmaf(nodes[i * INF + k], We[k * L + j], s);
    g_h[i * L + j] = s;
}

// ---------------- MLP layer via packed FFMA2 -------------------------------
// out = relu(in @ W + b) [* rowscale]. 64 nodes/block, 256 threads,
// thread = (tx feature-group of 4, ty node-group of 8).
// k processed in pairs: LDS.64 gives (a_k, a_{k+1}); acc keeps two partial
// sums per (node,feat) that are added in the epilogue.
__global__ void __launch_bounds__(256) mlp_kernel(const float* __restrict__ in,
                                                  const float* __restrict__ W,
                                                  const float* __restrict__ b,
                                                  float* __restrict__ out,
                                                  const float* __restrict__ rowscale,
                                                  int n) {
    __shared__ float sh[64 * L];
    const int tid = threadIdx.x;
    const int node0 = blockIdx.x * 64;
    const float4* in4 = (const float4*)in;
    float4* sh4 = (float4*)sh;
    #pragma unroll
    for (int it = 0; it < 8; it++) {
        int v = tid + it * 256;                 // float4 index; row = v/32
        int row = v >> 5, c = v & 31;
        float4 val = make_float4(0.f, 0.f, 0.f, 0.f);
        if (node0 + row < n) val = in4[(size_t)(node0 + row) * 32 + c];
        sh4[v] = val;
    }
    __syncthreads();
    const int tx = tid & 31, ty = tid >> 5;
    ull acc[8][4];
    #pragma unroll
    for (int i = 0; i < 8; i++)
        #pragma unroll
        for (int f = 0; f < 4; f++) acc[i][f] = 0ull;

    const float* shrow = sh + ty * 8 * L;
    #pragma unroll 4
    for (int k = 0; k < L; k += 2) {
        float4 w0 = __ldg((const float4*)&W[(k + 0) * L + tx * 4]);
        float4 w1 = __ldg((const float4*)&W[(k + 1) * L + tx * 4]);
        ull wx = pk2(w0.x, w1.x);
        ull wy = pk2(w0.y, w1.y);
        ull wz = pk2(w0.z, w1.z);
        ull ww = pk2(w0.w, w1.w);
        #pragma unroll
        for (int i = 0; i < 8; i++) {
            ull a2 = *(const ull*)&shrow[i * L + k];   // broadcast LDS.64
            acc[i][0] = ffma2(a2, wx, acc[i][0]);
            acc[i][1] = ffma2(a2, wy, acc[i][1]);
            acc[i][2] = ffma2(a2, wz, acc[i][2]);
            acc[i][3] = ffma2(a2, ww, acc[i][3]);
        }
    }
    float4 bb = __ldg((const float4*)&b[tx * 4]);
    #pragma unroll
    for (int i = 0; i < 8; i++) {
        int node = node0 + ty * 8 + i;
        if (node < n) {
            float2 p0 = upk2(acc[i][0]);
            float2 p1 = upk2(acc[i][1]);
            float2 p2 = upk2(acc[i][2]);
            float2 p3 = upk2(acc[i][3]);
            float4 o;
            o.x = fmaxf(p0.x + p0.y + bb.x, 0.f);
            o.y = fmaxf(p1.x + p1.y + bb.y, 0.f);
            o.z = fmaxf(p2.x + p2.y + bb.z, 0.f);
            o.w = fmaxf(p3.x + p3.y + bb.w, 0.f);
            if (rowscale) {
                float rs = rowscale[node];
                o.x *= rs; o.y *= rs; o.z *= rs; o.w *= rs;
            }
            *(float4*)&out[(size_t)node * L + tx * 4] = o;
        }
    }
}

// ---------------- aggregation + skip + layernorm (warp per node) ----------
// x rows are pre-scaled by inv_sqrt_s in the MLP epilogue. LAST step fuses
// the decoder and writes the final [n, INF] output instead of g_h.
template <bool LAST>
__global__ void agg_ln_kernel(const float* __restrict__ x,
                              const float* __restrict__ scale,
                              const float* __restrict__ bias,
                              const float* __restrict__ Wd,
                              const float* __restrict__ bd,
                              float* __restrict__ out, int n) {
    const int lane = threadIdx.x & 31;
    const int node = blockIdx.x * (blockDim.x >> 5) + (threadIdx.x >> 5);
    if (node >= n) return;
    const int start = g_row[node];
    const int deg = g_deg_r[node];
    float a0 = 0.f, a1 = 0.f, a2 = 0.f, a3 = 0.f;
    int j = 0;
    for (; j + 1 < deg; j += 2) {
        int s0 = g_csr_sender[start + j];
        int s1 = g_csr_sender[start + j + 1];
        float4 x0 = *(const float4*)&x[(size_t)s0 * L + lane * 4];
        float4 x1 = *(const float4*)&x[(size_t)s1 * L + lane * 4];
        a0 += x0.x + x1.x; a1 += x0.y + x1.y;
        a2 += x0.z + x1.z; a3 += x0.w + x1.w;
    }
    if (j < deg) {
        int s0 = g_csr_sender[start + j];
        float4 x0 = *(const float4*)&x[(size_t)s0 * L + lane * 4];
        a0 += x0.x; a1 += x0.y; a2 += x0.z; a3 += x0.w;
    }
    float wr = g_inv_r[node];
    float4 hv = *(const float4*)&g_h[(size_t)node * L + lane * 4];
    float v0 = hv.x + wr * a0;
    float v1 = hv.y + wr * a1;
    float v2 = hv.z + wr * a2;
    float v3 = hv.w + wr * a3;
    float sum = v0 + v1 + v2 + v3;
    float sq  = v0*v0 + v1*v1 + v2*v2 + v3*v3;
    #pragma unroll
    for (int off = 16; off >= 1; off >>= 1) {
        sum += __shfl_xor_sync(0xFFFFFFFF, sum, off);
        sq  += __shfl_xor_sync(0xFFFFFFFF, sq, off);
    }
    float mean = sum * (1.0f / L);
    float var  = sq * (1.0f / L) - mean * mean;
    float rstd = rsqrtf(var + 1e-6f);
    int f = lane * 4;
    float o0 = (v0 - mean) * rstd * scale[f + 0] + bias[f + 0];
    float o1 = (v1 - mean) * rstd * scale[f + 1] + bias[f + 1];
    float o2 = (v2 - mean) * rstd * scale[f + 2] + bias[f + 2];
    float o3 = (v3 - mean) * rstd * scale[f + 3] + bias[f + 3];
    if (!LAST) {
        *(float4*)&g_h[(size_t)node * L + lane * 4] = make_float4(o0, o1, o2, o3);
    } else {
        // fused decoder: out[node, j] = sum_k h[node,k] * Wd[k, j] + bd[j]
        float r[INF];
        #pragma unroll
        for (int jj = 0; jj < INF; jj++) {
            float p = o0 * Wd[(f + 0) * INF + jj]
                    + o1 * Wd[(f + 1) * INF + jj]
                    + o2 * Wd[(f + 2) * INF + jj]
                    + o3 * Wd[(f + 3) * INF + jj];
            #pragma unroll
            for (int off = 16; off >= 1; off >>= 1)
                p += __shfl_xor_sync(0xFFFFFFFF, p, off);
            r[jj] = p;
        }
        if (lane < INF) out[node * INF + lane] = r[lane] + bd[lane];
    }
}

// ---------------- launch ----------------
extern "C" void kernel_launch(void* const* d_in, const int* in_sizes, int n_in,
                              void* d_out, int out_size) {
    const float* nodes     = (const float*)d_in[0];
    const int*   senders   = (const int*)d_in[1];
    const int*   receivers = (const int*)d_in[2];
    const float* W_embed   = (const float*)d_in[3];
    const float* b_embed   = (const float*)d_in[4];
    const float* mlp_W     = (const float*)d_in[5];
    const float* mlp_b     = (const float*)d_in[6];
    const float* ln_scale  = (const float*)d_in[7];
    const float* ln_bias   = (const float*)d_in[8];
    const float* W_dec     = (const float*)d_in[9];
    const float* b_dec     = (const float*)d_in[10];
    float* out = (float*)d_out;

    const int n = in_sizes[0] / INF;
    const int e = in_sizes[1];

    zero_kernel<<<256, 256>>>(n);
    degree_kernel<<<(e + 255) / 256, 256>>>(senders, receivers, e);
    inv_row_kernel<<<(n + 255) / 256, 256>>>(n);
    fill_kernel<<<(e + 255) / 256, 256>>>(senders, receivers, e);

    float* d_h;   cudaGetSymbolAddress((void**)&d_h, g_h);
    float* d_t0;  cudaGetSymbolAddress((void**)&d_t0, g_t0);
    float* d_t1;  cudaGetSymbolAddress((void**)&d_t1, g_t1);
    float* d_invs; cudaGetSymbolAddress((void**)&d_invs, g_inv_s);

    embed_kernel<<<(n + 1) / 2, 256>>>(nodes, W_embed, b_embed, n);

    const int mlp_blocks = (n + 63) / 64;
    const int warp_blocks = (n + 7) / 8;   // 8 warps / 256-thread block
    for (int step = 0; step < 3; step++) {
        const float* W0 = mlp_W + (size_t)(step * 2 + 0) * L * L;
        const float* W1 = mlp_W + (size_t)(step * 2 + 1) * L * L;
        const float* b0 = mlp_b + (size_t)(step * 2 + 0) * L;
        const float* b1 = mlp_b + (size_t)(step * 2 + 1) * L;
        mlp_kernel<<<mlp_blocks, 256>>>(d_h, W0, b0, d_t0, nullptr, n);
        mlp_kernel<<<mlp_blocks, 256>>>(d_t0, W1, b1, d_t1, d_invs, n);
        if (step < 2) {
            agg_ln_kernel<false><<<warp_blocks, 256>>>(
                d_t1, ln_scale + step * L, ln_bias + step * L,
                nullptr, nullptr, nullptr, n);
        } else {
            agg_ln_kernel<true><<<warp_blocks, 256>>>(
                d_t1, ln_scale + step * L, ln_bias + step * L,
                W_dec, b_dec, out, n);
        }
    }
}